// round 10
// baseline (speedup 1.0000x reference)
#include <cuda_runtime.h>

#define Wd 384
#define Hd 256
#define HWD (Wd*Hd)

// Output: (N=2, A2=49, C=3, H, W) fp32
// Input0: low_rank (N, L=3, R=4, C=3, H, W) fp32 ; Input1: planes (N, L)
//
// Identity grid + constant per-(n,l,view) shift; taps/weights pixel-independent;
// borders via clamped load addresses. Lane owns 4 pixels (x..x+3), float4
// loads; neighbor columns via __shfl; lanes 0/31 load clamped halo.
// BRANCH-FREE view math: 8-wide E[] always; patterns A/B differ only in views
// 0 and 6 -> resolved with FSELs on (E, D) + unified weights w0 = 3s+a0,
// w6 = a6-3s  (a0,a6 encode the pattern).

__global__ __launch_bounds__(256, 2)
void lf4u_kernel(const float* __restrict__ lr,
                 const float* __restrict__ planes,
                 float* __restrict__ out)
{
    const int lane = threadIdx.x;
    const int XB = blockIdx.x * 128;
    const int x  = XB + lane * 4;
    const int y  = blockIdx.y * 8 + threadIdx.y;
    const int z  = blockIdx.z;                 // n*21 + kq*3 + c
    const int n  = z / 21;
    const int zc = z - n * 21;
    const int kq = zc / 3;
    const int c  = zc - kq * 3;

    const float cy = 255.0f / 512.0f;
    const float cx = 383.0f / 768.0f;

    const bool isL = (lane == 0), isR = (lane == 31);
    const bool edge = isL || isR;
    const int h0 = isR ? min(x + 4, Wd - 1) : max(x - 2, 0);
    const int h1 = isR ? min(x + 5, Wd - 1) : max(x - 1, 0);

    const float* basec = lr + (size_t)(n * 36 + c) * HWD;

    float wy_l[3];
    float w0_l[3], w1_l[3], w2_l[3], w4_l[3], w5_l[3], w6_l[3];
    bool  armB_l[3];
    int lo_l[3], hi_l[3];
#pragma unroll
    for (int l = 0; l < 3; l++) {
        float p   = __ldg(planes + n * 3 + l);
        float dyv = p * cy * (float)(3 - kq);
        float fy  = floorf(dyv);
        wy_l[l]   = dyv - fy;
        int iy0   = y + (int)fy;
        lo_l[l] = l * (12 * HWD) + min(max(iy0,     0), Hd - 1) * Wd;
        hi_l[l] = l * (12 * HWD) + min(max(iy0 + 1, 0), Hd - 1) * Wd;
        float s = p * cx;
        bool b  = (3.0f * s > 1.0f);
        armB_l[l] = b;
        w0_l[l] = fmaf(3.0f, s, b ? -1.0f : 0.0f);
        w1_l[l] = 2.0f * s;
        w2_l[l] = s;
        w4_l[l] = 1.0f - s;
        w5_l[l] = fmaf(-2.0f, s, 1.0f);
        w6_l[l] = fmaf(-3.0f, s, b ? 2.0f : 1.0f);
    }

    float sum[4][7];
#pragma unroll
    for (int p = 0; p < 4; p++)
#pragma unroll
        for (int v = 0; v < 7; v++) sum[p][v] = 0.0f;

    int roff = 0;
#pragma unroll 1
    for (int r = 0; r < 4; r++, roff += 3 * HWD) {
        // upfront batched loads: own float4 pairs (all layers) + edge halo
        float4 A[3], B[3];
#pragma unroll
        for (int l = 0; l < 3; l++) {
            A[l] = __ldg((const float4*)(basec + (roff + lo_l[l] + x)));
            B[l] = __ldg((const float4*)(basec + (roff + hi_l[l] + x)));
        }
        float ha0[3], ha1[3], hb0[3], hb1[3];
        if (edge) {
#pragma unroll
            for (int l = 0; l < 3; l++) {
                ha0[l] = __ldg(basec + (roff + lo_l[l] + h0));
                ha1[l] = __ldg(basec + (roff + lo_l[l] + h1));
                hb0[l] = __ldg(basec + (roff + hi_l[l] + h0));
                hb1[l] = __ldg(basec + (roff + hi_l[l] + h1));
            }
        }

        float prod[4][7];
#pragma unroll
        for (int l = 0; l < 3; l++) {
            const float wy = wy_l[l];
            const bool armB = armB_l[l];
            const float w0 = w0_l[l], w1 = w1_l[l], w2 = w2_l[l];
            const float w4 = w4_l[l], w5 = w5_l[l], w6 = w6_l[l];

            // column interps E[0..7] = cols x-2 .. x+5
            float E[8];
            E[2] = fmaf(wy, B[l].x - A[l].x, A[l].x);
            E[3] = fmaf(wy, B[l].y - A[l].y, A[l].y);
            E[4] = fmaf(wy, B[l].z - A[l].z, A[l].z);
            E[5] = fmaf(wy, B[l].w - A[l].w, A[l].w);
            E[1] = __shfl_up_sync(0xffffffffu, E[5], 1);    // col x-1
            E[0] = __shfl_up_sync(0xffffffffu, E[4], 1);    // col x-2
            E[6] = __shfl_down_sync(0xffffffffu, E[2], 1);  // col x+4
            E[7] = __shfl_down_sync(0xffffffffu, E[3], 1);  // col x+5
            if (edge) {
                float hP0 = fmaf(wy, hb0[l] - ha0[l], ha0[l]);
                float hP1 = fmaf(wy, hb1[l] - ha1[l], ha1[l]);
                if (isL) { E[0] = hP0; E[1] = hP1; }
                else     { E[6] = hP0; E[7] = hP1; }
            }

            float D[7];
#pragma unroll
            for (int j = 0; j < 7; j++) D[j] = E[j + 1] - E[j];

#pragma unroll
            for (int p = 0; p < 4; p++) {
                // v0 / v6 pattern-resolved with FSELs (branch-free)
                float Ev0 = armB ? E[p + 3] : E[p + 2];
                float Dv0 = armB ? D[p + 3] : D[p + 2];
                float Ev6 = armB ? E[p]     : E[p + 1];
                float Dv6 = armB ? D[p]     : D[p + 1];

                float va[7];
                va[0] = fmaf(w0, Dv0,      Ev0);
                va[1] = fmaf(w1, D[p + 2], E[p + 2]);
                va[2] = fmaf(w2, D[p + 2], E[p + 2]);
                va[3] = E[p + 2];
                va[4] = fmaf(w4, D[p + 1], E[p + 1]);
                va[5] = fmaf(w5, D[p + 1], E[p + 1]);
                va[6] = fmaf(w6, Dv6,      Ev6);

                if (l == 0) {
#pragma unroll
                    for (int v = 0; v < 7; v++) prod[p][v] = va[v];
                } else if (l == 1) {
#pragma unroll
                    for (int v = 0; v < 7; v++) prod[p][v] *= va[v];
                } else {
#pragma unroll
                    for (int v = 0; v < 7; v++)
                        sum[p][v] = fmaf(prod[p][v], va[v], sum[p][v]);
                }
            }
        }
    }

    // write (N, A2, C, H, W); a = kq*7 + lq ; 4 pixels -> STG.128
    float* o = out + ((size_t)((n * 49 + kq * 7) * 3 + c)) * HWD + y * Wd + x;
#pragma unroll
    for (int lq = 0; lq < 7; lq++) {
        float4 v = make_float4(sum[0][lq] * 0.25f, sum[1][lq] * 0.25f,
                               sum[2][lq] * 0.25f, sum[3][lq] * 0.25f);
        *(float4*)(o + (size_t)lq * 3 * HWD) = v;
    }
}

extern "C" void kernel_launch(void* const* d_in, const int* in_sizes, int n_in,
                              void* d_out, int out_size)
{
    const float* low_rank = (const float*)d_in[0];
    const float* planes   = (const float*)d_in[1];
    float* out = (float*)d_out;

    dim3 block(32, 8, 1);
    dim3 grid(Wd / 128, Hd / 8, 42);   // z = n*21 + kq*3 + c, N=2
    lf4u_kernel<<<grid, block>>>(low_rank, planes, out);
}

// round 11
// speedup vs baseline: 1.0448x; 1.0448x over previous
#include <cuda_runtime.h>

#define Wd 384
#define Hd 256
#define HWD (Wd*Hd)

// Output: (N=2, A2=49, C=3, H, W) fp32
// Input0: low_rank (N, L=3, R=4, C=3, H, W) fp32 ; Input1: planes (N, L)
//
// Identity grid + constant per-(n,l,view) shift; taps/weights pixel-independent;
// borders via clamped load addresses. Lane owns 4 pixels (x..x+3), float4
// loads; neighbor columns via __shfl; lanes 0/31 load clamped halo.
// Views 1-5 are pattern-independent (computed unconditionally); only views
// 0 and 6 sit inside the (warp-uniform) pattern branch. Accumulator updates
// are mode-specialized (UPD) -> no va[] intermediate, no copy MOVs.

// l is a compile-time constant after full unroll of the layer loop.
#define UPD(p, v, expr) do {                                         \
        float _t = (expr);                                           \
        if (l == 0)      prod[p][v] = _t;                            \
        else if (l == 1) prod[p][v] *= _t;                           \
        else             sum[p][v] = fmaf(prod[p][v], _t, sum[p][v]);\
    } while (0)

__global__ __launch_bounds__(256, 2)
void lf4v_kernel(const float* __restrict__ lr,
                 const float* __restrict__ planes,
                 float* __restrict__ out)
{
    const int lane = threadIdx.x;
    const int XB = blockIdx.x * 128;
    const int x  = XB + lane * 4;
    const int y  = blockIdx.y * 8 + threadIdx.y;
    const int z  = blockIdx.z;                 // n*21 + kq*3 + c
    const int n  = z / 21;
    const int zc = z - n * 21;
    const int kq = zc / 3;
    const int c  = zc - kq * 3;

    const float cy = 255.0f / 512.0f;
    const float cx = 383.0f / 768.0f;

    const bool isL = (lane == 0), isR = (lane == 31);
    const bool edge = isL || isR;
    const int h0 = isR ? min(x + 4, Wd - 1) : max(x - 2, 0);
    const int h1 = isR ? min(x + 5, Wd - 1) : max(x - 1, 0);

    const float* basec = lr + (size_t)(n * 36 + c) * HWD;

    float wy_l[3];
    float w0_l[3], w1_l[3], w2_l[3], w4_l[3], w5_l[3], w6_l[3];
    bool  armB_l[3];
    int lo_l[3], hi_l[3];
#pragma unroll
    for (int l = 0; l < 3; l++) {
        float p   = __ldg(planes + n * 3 + l);
        float dyv = p * cy * (float)(3 - kq);
        float fy  = floorf(dyv);
        wy_l[l]   = dyv - fy;
        int iy0   = y + (int)fy;
        lo_l[l] = l * (12 * HWD) + min(max(iy0,     0), Hd - 1) * Wd;
        hi_l[l] = l * (12 * HWD) + min(max(iy0 + 1, 0), Hd - 1) * Wd;
        float s = p * cx;
        bool b  = (3.0f * s > 1.0f);
        armB_l[l] = b;
        w0_l[l] = fmaf(3.0f, s, b ? -1.0f : 0.0f);
        w1_l[l] = 2.0f * s;
        w2_l[l] = s;
        w4_l[l] = 1.0f - s;
        w5_l[l] = fmaf(-2.0f, s, 1.0f);
        w6_l[l] = fmaf(-3.0f, s, b ? 2.0f : 1.0f);
    }

    float sum[4][7];
#pragma unroll
    for (int p = 0; p < 4; p++)
#pragma unroll
        for (int v = 0; v < 7; v++) sum[p][v] = 0.0f;

    int roff = 0;
#pragma unroll 1
    for (int r = 0; r < 4; r++, roff += 3 * HWD) {
        // upfront batched loads: own float4 pairs (all layers) + edge halo
        float4 A[3], B[3];
#pragma unroll
        for (int l = 0; l < 3; l++) {
            A[l] = __ldg((const float4*)(basec + (roff + lo_l[l] + x)));
            B[l] = __ldg((const float4*)(basec + (roff + hi_l[l] + x)));
        }
        float ha0[3], ha1[3], hb0[3], hb1[3];
        if (edge) {
#pragma unroll
            for (int l = 0; l < 3; l++) {
                ha0[l] = __ldg(basec + (roff + lo_l[l] + h0));
                ha1[l] = __ldg(basec + (roff + lo_l[l] + h1));
                hb0[l] = __ldg(basec + (roff + hi_l[l] + h0));
                hb1[l] = __ldg(basec + (roff + hi_l[l] + h1));
            }
        }

        float prod[4][7];
#pragma unroll
        for (int l = 0; l < 3; l++) {
            const float wy = wy_l[l];
            const float w0 = w0_l[l], w1 = w1_l[l], w2 = w2_l[l];
            const float w4 = w4_l[l], w5 = w5_l[l], w6 = w6_l[l];

            // column interps E[0..7] = cols x-2 .. x+5
            float E[8];
            E[2] = fmaf(wy, B[l].x - A[l].x, A[l].x);
            E[3] = fmaf(wy, B[l].y - A[l].y, A[l].y);
            E[4] = fmaf(wy, B[l].z - A[l].z, A[l].z);
            E[5] = fmaf(wy, B[l].w - A[l].w, A[l].w);
            E[1] = __shfl_up_sync(0xffffffffu, E[5], 1);    // col x-1
            E[0] = __shfl_up_sync(0xffffffffu, E[4], 1);    // col x-2
            E[6] = __shfl_down_sync(0xffffffffu, E[2], 1);  // col x+4
            E[7] = __shfl_down_sync(0xffffffffu, E[3], 1);  // col x+5
            if (edge) {
                float hP0 = fmaf(wy, hb0[l] - ha0[l], ha0[l]);
                float hP1 = fmaf(wy, hb1[l] - ha1[l], ha1[l]);
                if (isL) { E[0] = hP0; E[1] = hP1; }
                else     { E[6] = hP0; E[7] = hP1; }
            }

            float D[7];
#pragma unroll
            for (int j = 0; j < 7; j++) D[j] = E[j + 1] - E[j];

            // views 1-5: pattern-independent
#pragma unroll
            for (int p = 0; p < 4; p++) {
                UPD(p, 1, fmaf(w1, D[p + 2], E[p + 2]));
                UPD(p, 2, fmaf(w2, D[p + 2], E[p + 2]));
                UPD(p, 3, E[p + 2]);
                UPD(p, 4, fmaf(w4, D[p + 1], E[p + 1]));
                UPD(p, 5, fmaf(w5, D[p + 1], E[p + 1]));
            }
            // views 0 & 6: pattern-dependent taps (warp-uniform branch)
            if (!armB_l[l]) {
#pragma unroll
                for (int p = 0; p < 4; p++) {
                    UPD(p, 0, fmaf(w0, D[p + 2], E[p + 2]));
                    UPD(p, 6, fmaf(w6, D[p + 1], E[p + 1]));
                }
            } else {
#pragma unroll
                for (int p = 0; p < 4; p++) {
                    UPD(p, 0, fmaf(w0, D[p + 3], E[p + 3]));
                    UPD(p, 6, fmaf(w6, D[p],     E[p]));
                }
            }
        }
    }

    // write (N, A2, C, H, W); a = kq*7 + lq ; 4 pixels -> STG.128
    float* o = out + ((size_t)((n * 49 + kq * 7) * 3 + c)) * HWD + y * Wd + x;
#pragma unroll
    for (int lq = 0; lq < 7; lq++) {
        float4 v = make_float4(sum[0][lq] * 0.25f, sum[1][lq] * 0.25f,
                               sum[2][lq] * 0.25f, sum[3][lq] * 0.25f);
        *(float4*)(o + (size_t)lq * 3 * HWD) = v;
    }
}

extern "C" void kernel_launch(void* const* d_in, const int* in_sizes, int n_in,
                              void* d_out, int out_size)
{
    const float* low_rank = (const float*)d_in[0];
    const float* planes   = (const float*)d_in[1];
    float* out = (float*)d_out;

    dim3 block(32, 8, 1);
    dim3 grid(Wd / 128, Hd / 8, 42);   // z = n*21 + kq*3 + c, N=2
    lf4v_kernel<<<grid, block>>>(low_rank, planes, out);
}

// round 13
// speedup vs baseline: 1.0478x; 1.0029x over previous
#include <cuda_runtime.h>

#define Wd 384
#define Hd 256
#define HWD (Wd*Hd)

// Output: (N=2, A2=49, C=3, H, W) fp32
// Input0: low_rank (N, L=3, R=4, C=3, H, W) fp32 ; Input1: planes (N, L)
//
// Identity grid + constant per-(n,l,view) shift; taps/weights pixel-independent;
// borders via clamped load addresses. Lane owns 4 pixels (x..x+3), float4
// loads; neighbor columns via __shfl; lanes 0/31 use clamped halo values.
// R12: 128-thread blocks + launch_bounds(128,5) (102-reg ceiling, 20 warps/SM);
// per-slice edge merge is branchless (SEL), halo loads once per r under if(edge).

// l is a compile-time constant after full unroll of the layer loop.
#define UPD(p, v, expr) do {                                         \
        float _t = (expr);                                           \
        if (l == 0)      prod[p][v] = _t;                            \
        else if (l == 1) prod[p][v] *= _t;                           \
        else             sum[p][v] = fmaf(prod[p][v], _t, sum[p][v]);\
    } while (0)

__global__ __launch_bounds__(128, 5)
void lf4w_kernel(const float* __restrict__ lr,
                 const float* __restrict__ planes,
                 float* __restrict__ out)
{
    const int lane = threadIdx.x;
    const int XB = blockIdx.x * 128;
    const int x  = XB + lane * 4;
    const int y  = blockIdx.y * 4 + threadIdx.y;
    const int z  = blockIdx.z;                 // n*21 + kq*3 + c
    const int n  = z / 21;
    const int zc = z - n * 21;
    const int kq = zc / 3;
    const int c  = zc - kq * 3;

    const float cy = 255.0f / 512.0f;
    const float cx = 383.0f / 768.0f;

    const bool isL = (lane == 0), isR = (lane == 31);
    const bool edge = isL || isR;
    const int h0 = isR ? min(x + 4, Wd - 1) : max(x - 2, 0);
    const int h1 = isR ? min(x + 5, Wd - 1) : max(x - 1, 0);

    const float* basec = lr + (size_t)(n * 36 + c) * HWD;

    float wy_l[3];
    float w0_l[3], w1_l[3], w2_l[3], w4_l[3], w5_l[3], w6_l[3];
    bool  armB_l[3];
    int lo_l[3], hi_l[3];
#pragma unroll
    for (int l = 0; l < 3; l++) {
        float p   = __ldg(planes + n * 3 + l);
        float dyv = p * cy * (float)(3 - kq);
        float fy  = floorf(dyv);
        wy_l[l]   = dyv - fy;
        int iy0   = y + (int)fy;
        lo_l[l] = l * (12 * HWD) + min(max(iy0,     0), Hd - 1) * Wd;
        hi_l[l] = l * (12 * HWD) + min(max(iy0 + 1, 0), Hd - 1) * Wd;
        float s = p * cx;
        bool b  = (3.0f * s > 1.0f);
        armB_l[l] = b;
        w0_l[l] = fmaf(3.0f, s, b ? -1.0f : 0.0f);
        w1_l[l] = 2.0f * s;
        w2_l[l] = s;
        w4_l[l] = 1.0f - s;
        w5_l[l] = fmaf(-2.0f, s, 1.0f);
        w6_l[l] = fmaf(-3.0f, s, b ? 2.0f : 1.0f);
    }

    float sum[4][7];
#pragma unroll
    for (int p = 0; p < 4; p++)
#pragma unroll
        for (int v = 0; v < 7; v++) sum[p][v] = 0.0f;

    // halo regs (only meaningful for lanes 0/31; zero elsewhere)
    float ha0[3] = {0.f, 0.f, 0.f}, ha1[3] = {0.f, 0.f, 0.f};
    float hb0[3] = {0.f, 0.f, 0.f}, hb1[3] = {0.f, 0.f, 0.f};

    int roff = 0;
#pragma unroll 1
    for (int r = 0; r < 4; r++, roff += 3 * HWD) {
        // upfront batched loads: own float4 pairs (all layers) + edge halo
        float4 A[3], B[3];
#pragma unroll
        for (int l = 0; l < 3; l++) {
            A[l] = __ldg((const float4*)(basec + (roff + lo_l[l] + x)));
            B[l] = __ldg((const float4*)(basec + (roff + hi_l[l] + x)));
        }
        if (edge) {
#pragma unroll
            for (int l = 0; l < 3; l++) {
                ha0[l] = __ldg(basec + (roff + lo_l[l] + h0));
                ha1[l] = __ldg(basec + (roff + lo_l[l] + h1));
                hb0[l] = __ldg(basec + (roff + hi_l[l] + h0));
                hb1[l] = __ldg(basec + (roff + hi_l[l] + h1));
            }
        }

        float prod[4][7];
#pragma unroll
        for (int l = 0; l < 3; l++) {
            const float wy = wy_l[l];
            const float w0 = w0_l[l], w1 = w1_l[l], w2 = w2_l[l];
            const float w4 = w4_l[l], w5 = w5_l[l], w6 = w6_l[l];

            // column interps E[0..7] = cols x-2 .. x+5
            float E[8];
            E[2] = fmaf(wy, B[l].x - A[l].x, A[l].x);
            E[3] = fmaf(wy, B[l].y - A[l].y, A[l].y);
            E[4] = fmaf(wy, B[l].z - A[l].z, A[l].z);
            E[5] = fmaf(wy, B[l].w - A[l].w, A[l].w);
            E[1] = __shfl_up_sync(0xffffffffu, E[5], 1);    // col x-1
            E[0] = __shfl_up_sync(0xffffffffu, E[4], 1);    // col x-2
            E[6] = __shfl_down_sync(0xffffffffu, E[2], 1);  // col x+4
            E[7] = __shfl_down_sync(0xffffffffu, E[3], 1);  // col x+5

            // branchless edge merge (SELs; hP garbage for non-edge, discarded)
            {
                float hP0 = fmaf(wy, hb0[l] - ha0[l], ha0[l]);
                float hP1 = fmaf(wy, hb1[l] - ha1[l], ha1[l]);
                E[0] = isL ? hP0 : E[0];
                E[1] = isL ? hP1 : E[1];
                E[6] = isR ? hP0 : E[6];
                E[7] = isR ? hP1 : E[7];
            }

            float D[7];
#pragma unroll
            for (int j = 0; j < 7; j++) D[j] = E[j + 1] - E[j];

            // views 1-5: pattern-independent
#pragma unroll
            for (int p = 0; p < 4; p++) {
                UPD(p, 1, fmaf(w1, D[p + 2], E[p + 2]));
                UPD(p, 2, fmaf(w2, D[p + 2], E[p + 2]));
                UPD(p, 3, E[p + 2]);
                UPD(p, 4, fmaf(w4, D[p + 1], E[p + 1]));
                UPD(p, 5, fmaf(w5, D[p + 1], E[p + 1]));
            }
            // views 0 & 6: pattern-dependent taps (warp-uniform branch)
            if (!armB_l[l]) {
#pragma unroll
                for (int p = 0; p < 4; p++) {
                    UPD(p, 0, fmaf(w0, D[p + 2], E[p + 2]));
                    UPD(p, 6, fmaf(w6, D[p + 1], E[p + 1]));
                }
            } else {
#pragma unroll
                for (int p = 0; p < 4; p++) {
                    UPD(p, 0, fmaf(w0, D[p + 3], E[p + 3]));
                    UPD(p, 6, fmaf(w6, D[p],     E[p]));
                }
            }
        }
    }

    // write (N, A2, C, H, W); a = kq*7 + lq ; 4 pixels -> STG.128
    float* o = out + ((size_t)((n * 49 + kq * 7) * 3 + c)) * HWD + y * Wd + x;
#pragma unroll
    for (int lq = 0; lq < 7; lq++) {
        float4 v = make_float4(sum[0][lq] * 0.25f, sum[1][lq] * 0.25f,
                               sum[2][lq] * 0.25f, sum[3][lq] * 0.25f);
        *(float4*)(o + (size_t)lq * 3 * HWD) = v;
    }
}

extern "C" void kernel_launch(void* const* d_in, const int* in_sizes, int n_in,
                              void* d_out, int out_size)
{
    const float* low_rank = (const float*)d_in[0];
    const float* planes   = (const float*)d_in[1];
    float* out = (float*)d_out;

    dim3 block(32, 4, 1);
    dim3 grid(Wd / 128, Hd / 4, 42);   // z = n*21 + kq*3 + c, N=2
    lf4w_kernel<<<grid, block>>>(low_rank, planes, out);
}

// round 15
// speedup vs baseline: 1.1740x; 1.1204x over previous
#include <cuda_runtime.h>

#define Wd 384
#define Hd 256
#define HWD (Wd*Hd)

// Output: (N=2, A2=49, C=3, H, W) fp32
// Input0: low_rank (N, L=3, R=4, C=3, H, W) fp32 ; Input1: planes (N, L)
//
// Identity grid + constant per-(n,l,view) shift; taps/weights pixel-independent;
// borders via clamped load addresses. Lane owns 4 pixels (x..x+3), float4
// loads; neighbor columns via __shfl; lanes 0/31 use clamped halo values.
// R14: rotating software prefetch — after slice (r,l) consumes A[l]/B[l] in the
// E-interp, the loads for (r+1,l) are issued into the SAME registers (WAR via
// scoreboard, zero extra regs). Halo prefetch for r+1 at end of each r body.

// l is a compile-time constant after full unroll of the layer loop.
#define UPD(p, v, expr) do {                                         \
        float _t = (expr);                                           \
        if (l == 0)      prod[p][v] = _t;                            \
        else if (l == 1) prod[p][v] *= _t;                           \
        else             sum[p][v] = fmaf(prod[p][v], _t, sum[p][v]);\
    } while (0)

__global__ __launch_bounds__(128, 4)
void lfpf_kernel(const float* __restrict__ lr,
                 const float* __restrict__ planes,
                 float* __restrict__ out)
{
    const int lane = threadIdx.x;
    const int XB = blockIdx.x * 128;
    const int x  = XB + lane * 4;
    const int y  = blockIdx.y * 4 + threadIdx.y;
    const int z  = blockIdx.z;                 // n*21 + kq*3 + c
    const int n  = z / 21;
    const int zc = z - n * 21;
    const int kq = zc / 3;
    const int c  = zc - kq * 3;

    const float cy = 255.0f / 512.0f;
    const float cx = 383.0f / 768.0f;

    const bool isL = (lane == 0), isR = (lane == 31);
    const bool edge = isL || isR;
    const int h0 = isR ? min(x + 4, Wd - 1) : max(x - 2, 0);
    const int h1 = isR ? min(x + 5, Wd - 1) : max(x - 1, 0);

    const float* basec = lr + (size_t)(n * 36 + c) * HWD;

    float wy_l[3];
    float w0_l[3], w1_l[3], w2_l[3], w4_l[3], w5_l[3], w6_l[3];
    bool  armB_l[3];
    int lo_l[3], hi_l[3];
#pragma unroll
    for (int l = 0; l < 3; l++) {
        float p   = __ldg(planes + n * 3 + l);
        float dyv = p * cy * (float)(3 - kq);
        float fy  = floorf(dyv);
        wy_l[l]   = dyv - fy;
        int iy0   = y + (int)fy;
        lo_l[l] = l * (12 * HWD) + min(max(iy0,     0), Hd - 1) * Wd;
        hi_l[l] = l * (12 * HWD) + min(max(iy0 + 1, 0), Hd - 1) * Wd;
        float s = p * cx;
        bool b  = (3.0f * s > 1.0f);
        armB_l[l] = b;
        w0_l[l] = fmaf(3.0f, s, b ? -1.0f : 0.0f);
        w1_l[l] = 2.0f * s;
        w2_l[l] = s;
        w4_l[l] = 1.0f - s;
        w5_l[l] = fmaf(-2.0f, s, 1.0f);
        w6_l[l] = fmaf(-3.0f, s, b ? 2.0f : 1.0f);
    }

    float sum[4][7];
#pragma unroll
    for (int p = 0; p < 4; p++)
#pragma unroll
        for (int v = 0; v < 7; v++) sum[p][v] = 0.0f;

    // halo regs (only meaningful for lanes 0/31; zero elsewhere)
    float ha0[3] = {0.f, 0.f, 0.f}, ha1[3] = {0.f, 0.f, 0.f};
    float hb0[3] = {0.f, 0.f, 0.f}, hb1[3] = {0.f, 0.f, 0.f};

    // prologue: loads for r=0
    float4 A[3], B[3];
#pragma unroll
    for (int l = 0; l < 3; l++) {
        A[l] = __ldg((const float4*)(basec + (lo_l[l] + x)));
        B[l] = __ldg((const float4*)(basec + (hi_l[l] + x)));
    }
    if (edge) {
#pragma unroll
        for (int l = 0; l < 3; l++) {
            ha0[l] = __ldg(basec + (lo_l[l] + h0));
            ha1[l] = __ldg(basec + (lo_l[l] + h1));
            hb0[l] = __ldg(basec + (hi_l[l] + h0));
            hb1[l] = __ldg(basec + (hi_l[l] + h1));
        }
    }

    int roff = 0;
#pragma unroll 1
    for (int r = 0; r < 4; r++, roff += 3 * HWD) {
        const int roffN = roff + ((r < 3) ? 3 * HWD : 0);   // r=3: harmless reload

        float prod[4][7];
#pragma unroll
        for (int l = 0; l < 3; l++) {
            const float wy = wy_l[l];
            const float w0 = w0_l[l], w1 = w1_l[l], w2 = w2_l[l];
            const float w4 = w4_l[l], w5 = w5_l[l], w6 = w6_l[l];

            // column interps E[0..7] = cols x-2 .. x+5 (consumes A[l]/B[l])
            float E[8];
            E[2] = fmaf(wy, B[l].x - A[l].x, A[l].x);
            E[3] = fmaf(wy, B[l].y - A[l].y, A[l].y);
            E[4] = fmaf(wy, B[l].z - A[l].z, A[l].z);
            E[5] = fmaf(wy, B[l].w - A[l].w, A[l].w);

            // rotating prefetch: next-r same-l into the just-freed registers
            A[l] = __ldg((const float4*)(basec + (roffN + lo_l[l] + x)));
            B[l] = __ldg((const float4*)(basec + (roffN + hi_l[l] + x)));

            E[1] = __shfl_up_sync(0xffffffffu, E[5], 1);    // col x-1
            E[0] = __shfl_up_sync(0xffffffffu, E[4], 1);    // col x-2
            E[6] = __shfl_down_sync(0xffffffffu, E[2], 1);  // col x+4
            E[7] = __shfl_down_sync(0xffffffffu, E[3], 1);  // col x+5

            // branchless edge merge (SELs; hP garbage for non-edge, discarded)
            {
                float hP0 = fmaf(wy, hb0[l] - ha0[l], ha0[l]);
                float hP1 = fmaf(wy, hb1[l] - ha1[l], ha1[l]);
                E[0] = isL ? hP0 : E[0];
                E[1] = isL ? hP1 : E[1];
                E[6] = isR ? hP0 : E[6];
                E[7] = isR ? hP1 : E[7];
            }

            float D[7];
#pragma unroll
            for (int j = 0; j < 7; j++) D[j] = E[j + 1] - E[j];

            // views 1-5: pattern-independent
#pragma unroll
            for (int p = 0; p < 4; p++) {
                UPD(p, 1, fmaf(w1, D[p + 2], E[p + 2]));
                UPD(p, 2, fmaf(w2, D[p + 2], E[p + 2]));
                UPD(p, 3, E[p + 2]);
                UPD(p, 4, fmaf(w4, D[p + 1], E[p + 1]));
                UPD(p, 5, fmaf(w5, D[p + 1], E[p + 1]));
            }
            // views 0 & 6: pattern-dependent taps (warp-uniform branch)
            if (!armB_l[l]) {
#pragma unroll
                for (int p = 0; p < 4; p++) {
                    UPD(p, 0, fmaf(w0, D[p + 2], E[p + 2]));
                    UPD(p, 6, fmaf(w6, D[p + 1], E[p + 1]));
                }
            } else {
#pragma unroll
                for (int p = 0; p < 4; p++) {
                    UPD(p, 0, fmaf(w0, D[p + 3], E[p + 3]));
                    UPD(p, 6, fmaf(w6, D[p],     E[p]));
                }
            }
        }

        // halo prefetch for next r (last halo use was early in slice l=2 above)
        if (edge) {
#pragma unroll
            for (int l = 0; l < 3; l++) {
                ha0[l] = __ldg(basec + (roffN + lo_l[l] + h0));
                ha1[l] = __ldg(basec + (roffN + lo_l[l] + h1));
                hb0[l] = __ldg(basec + (roffN + hi_l[l] + h0));
                hb1[l] = __ldg(basec + (roffN + hi_l[l] + h1));
            }
        }
    }

    // write (N, A2, C, H, W); a = kq*7 + lq ; 4 pixels -> STG.128
    float* o = out + ((size_t)((n * 49 + kq * 7) * 3 + c)) * HWD + y * Wd + x;
#pragma unroll
    for (int lq = 0; lq < 7; lq++) {
        float4 v = make_float4(sum[0][lq] * 0.25f, sum[1][lq] * 0.25f,
                               sum[2][lq] * 0.25f, sum[3][lq] * 0.25f);
        *(float4*)(o + (size_t)lq * 3 * HWD) = v;
    }
}

extern "C" void kernel_launch(void* const* d_in, const int* in_sizes, int n_in,
                              void* d_out, int out_size)
{
    const float* low_rank = (const float*)d_in[0];
    const float* planes   = (const float*)d_in[1];
    float* out = (float*)d_out;

    dim3 block(32, 4, 1);
    dim3 grid(Wd / 128, Hd / 4, 42);   // z = n*21 + kq*3 + c, N=2
    lfpf_kernel<<<grid, block>>>(low_rank, planes, out);
}

// round 16
// speedup vs baseline: 1.3578x; 1.1566x over previous
#include <cuda_runtime.h>

#define Wd 384
#define Hd 256
#define HWD (Wd*Hd)

// Output: (N=2, A2=49, C=3, H, W) fp32
// Input0: low_rank (N, L=3, R=4, C=3, H, W) fp32 ; Input1: planes (N, L)
//
// Identity grid + constant per-(n,l,view) shift; taps/weights pixel-independent;
// borders via clamped load addresses. Lane owns 4 pixels (x..x+3), float4
// loads; neighbor columns via __shfl; lanes 0/31 use clamped halo values.
// R16: rolling 64-bit pointers (one IADD64 per r each, bare [ptr] loads),
// float2 halo loads (contiguous clamped pair + border SEL fix),
// rotating register prefetch as in R15.

// l is a compile-time constant after full unroll of the layer loop.
#define UPD(p, v, expr) do {                                         \
        float _t = (expr);                                           \
        if (l == 0)      prod[p][v] = _t;                            \
        else if (l == 1) prod[p][v] *= _t;                           \
        else             sum[p][v] = fmaf(prod[p][v], _t, sum[p][v]);\
    } while (0)

__global__ __launch_bounds__(128, 4)
void lfrp_kernel(const float* __restrict__ lr,
                 const float* __restrict__ planes,
                 float* __restrict__ out)
{
    const int lane = threadIdx.x;
    const int XB = blockIdx.x * 128;
    const int x  = XB + lane * 4;
    const int y  = blockIdx.y * 4 + threadIdx.y;
    const int z  = blockIdx.z;                 // n*21 + kq*3 + c
    const int n  = z / 21;
    const int zc = z - n * 21;
    const int kq = zc / 3;
    const int c  = zc - kq * 3;

    const float cy = 255.0f / 512.0f;
    const float cx = 383.0f / 768.0f;

    const bool isL = (lane == 0), isR = (lane == 31);
    const bool edge = isL || isR;
    // contiguous clamped halo base (8B aligned); dh = element offset from x
    const int dh = (isR ? min(x + 4, Wd - 2) : max(x - 2, 0)) - x;
    const bool borderL = isL && (x == 0);         // halo cols both clamp to 0
    const bool borderR = isR && (x >= Wd - 4);    // halo cols both clamp to Wd-1

    const float* basec = lr + (size_t)(n * 36 + c) * HWD;

    float wy_l[3];
    float w0_l[3], w1_l[3], w2_l[3], w4_l[3], w5_l[3], w6_l[3];
    bool  armB_l[3];
    const float* pA[3];
    const float* pB[3];
#pragma unroll
    for (int l = 0; l < 3; l++) {
        float p   = __ldg(planes + n * 3 + l);
        float dyv = p * cy * (float)(3 - kq);
        float fy  = floorf(dyv);
        wy_l[l]   = dyv - fy;
        int iy0   = y + (int)fy;
        pA[l] = basec + (l * (12 * HWD) + min(max(iy0,     0), Hd - 1) * Wd + x);
        pB[l] = basec + (l * (12 * HWD) + min(max(iy0 + 1, 0), Hd - 1) * Wd + x);
        float s = p * cx;
        bool b  = (3.0f * s > 1.0f);
        armB_l[l] = b;
        w0_l[l] = fmaf(3.0f, s, b ? -1.0f : 0.0f);
        w1_l[l] = 2.0f * s;
        w2_l[l] = s;
        w4_l[l] = 1.0f - s;
        w5_l[l] = fmaf(-2.0f, s, 1.0f);
        w6_l[l] = fmaf(-3.0f, s, b ? 2.0f : 1.0f);
    }

    float sum[4][7];
#pragma unroll
    for (int p = 0; p < 4; p++)
#pragma unroll
        for (int v = 0; v < 7; v++) sum[p][v] = 0.0f;

    // halo pairs (lanes 0/31 only; garbage elsewhere, discarded by SELs)
    float2 ha[3], hb[3];
#pragma unroll
    for (int l = 0; l < 3; l++) { ha[l] = make_float2(0.f, 0.f); hb[l] = ha[l]; }

    // prologue: loads for r=0
    float4 A[3], B[3];
#pragma unroll
    for (int l = 0; l < 3; l++) {
        A[l] = __ldg((const float4*)pA[l]);
        B[l] = __ldg((const float4*)pB[l]);
    }
    if (edge) {
#pragma unroll
        for (int l = 0; l < 3; l++) {
            ha[l] = __ldg((const float2*)(pA[l] + dh));
            hb[l] = __ldg((const float2*)(pB[l] + dh));
        }
    }

#pragma unroll 1
    for (int r = 0; r < 4; r++) {
        const int step = (r < 3) ? 3 * HWD : 0;   // r=3: harmless reload

        float prod[4][7];
#pragma unroll
        for (int l = 0; l < 3; l++) {
            const float wy = wy_l[l];
            const float w0 = w0_l[l], w1 = w1_l[l], w2 = w2_l[l];
            const float w4 = w4_l[l], w5 = w5_l[l], w6 = w6_l[l];

            // column interps E[0..7] = cols x-2 .. x+5 (consumes A[l]/B[l])
            float E[8];
            E[2] = fmaf(wy, B[l].x - A[l].x, A[l].x);
            E[3] = fmaf(wy, B[l].y - A[l].y, A[l].y);
            E[4] = fmaf(wy, B[l].z - A[l].z, A[l].z);
            E[5] = fmaf(wy, B[l].w - A[l].w, A[l].w);

            // rotating prefetch: advance pointers, next-r same-l into freed regs
            pA[l] += step;
            pB[l] += step;
            A[l] = __ldg((const float4*)pA[l]);
            B[l] = __ldg((const float4*)pB[l]);

            E[1] = __shfl_up_sync(0xffffffffu, E[5], 1);    // col x-1
            E[0] = __shfl_up_sync(0xffffffffu, E[4], 1);    // col x-2
            E[6] = __shfl_down_sync(0xffffffffu, E[2], 1);  // col x+4
            E[7] = __shfl_down_sync(0xffffffffu, E[3], 1);  // col x+5

            // halo interp + border duplication fix + branchless merge
            {
                float hP0 = fmaf(wy, hb[l].x - ha[l].x, ha[l].x);
                float hP1 = fmaf(wy, hb[l].y - ha[l].y, ha[l].y);
                hP1 = borderL ? hP0 : hP1;   // cols {0,0}
                hP0 = borderR ? hP1 : hP0;   // cols {Wd-1,Wd-1}
                E[0] = isL ? hP0 : E[0];
                E[1] = isL ? hP1 : E[1];
                E[6] = isR ? hP0 : E[6];
                E[7] = isR ? hP1 : E[7];
            }

            float D[7];
#pragma unroll
            for (int j = 0; j < 7; j++) D[j] = E[j + 1] - E[j];

            // views 1-5: pattern-independent
#pragma unroll
            for (int p = 0; p < 4; p++) {
                UPD(p, 1, fmaf(w1, D[p + 2], E[p + 2]));
                UPD(p, 2, fmaf(w2, D[p + 2], E[p + 2]));
                UPD(p, 3, E[p + 2]);
                UPD(p, 4, fmaf(w4, D[p + 1], E[p + 1]));
                UPD(p, 5, fmaf(w5, D[p + 1], E[p + 1]));
            }
            // views 0 & 6: pattern-dependent taps (warp-uniform branch)
            if (!armB_l[l]) {
#pragma unroll
                for (int p = 0; p < 4; p++) {
                    UPD(p, 0, fmaf(w0, D[p + 2], E[p + 2]));
                    UPD(p, 6, fmaf(w6, D[p + 1], E[p + 1]));
                }
            } else {
#pragma unroll
                for (int p = 0; p < 4; p++) {
                    UPD(p, 0, fmaf(w0, D[p + 3], E[p + 3]));
                    UPD(p, 6, fmaf(w6, D[p],     E[p]));
                }
            }
        }

        // halo prefetch for next r (pointers already advanced)
        if (edge) {
#pragma unroll
            for (int l = 0; l < 3; l++) {
                ha[l] = __ldg((const float2*)(pA[l] + dh));
                hb[l] = __ldg((const float2*)(pB[l] + dh));
            }
        }
    }

    // write (N, A2, C, H, W); a = kq*7 + lq ; 4 pixels -> STG.128
    float* o = out + ((size_t)((n * 49 + kq * 7) * 3 + c)) * HWD + y * Wd + x;
#pragma unroll
    for (int lq = 0; lq < 7; lq++) {
        float4 v = make_float4(sum[0][lq] * 0.25f, sum[1][lq] * 0.25f,
                               sum[2][lq] * 0.25f, sum[3][lq] * 0.25f);
        *(float4*)(o + (size_t)lq * 3 * HWD) = v;
    }
}

extern "C" void kernel_launch(void* const* d_in, const int* in_sizes, int n_in,
                              void* d_out, int out_size)
{
    const float* low_rank = (const float*)d_in[0];
    const float* planes   = (const float*)d_in[1];
    float* out = (float*)d_out;

    dim3 block(32, 4, 1);
    dim3 grid(Wd / 128, Hd / 4, 42);   // z = n*21 + kq*3 + c, N=2
    lfrp_kernel<<<grid, block>>>(low_rank, planes, out);
}